// round 1
// baseline (speedup 1.0000x reference)
#include <cuda_runtime.h>

// shift op: x[32, 288, 64, 64] f32. cpg = 288/9 = 32.
// group g in 0..7: out[:, g*32:(g+1)*32, h, w] = x[same ch, h+dh, w+dw] (0 outside)
// group 8 (c in [256,288)): zeros.
//
// Layout is NCHW contiguous. Plane size H*W = 4096 floats.
// Block = 256 threads covers 16 rows of one (b,c) plane (16 float4-quads per row).
// grid.x = B*C*(H/16) = 32*288*4 = 36864.

#define SH_H 64
#define SH_W 64
#define SH_C 288
#define SH_CPG_SHIFT 5   // cpg = 32

__constant__ int c_dh[8] = {-1,  1,  0,  0, -1, -1,  1,  1};
__constant__ int c_dw[8] = { 0,  0, -1,  1, -1,  1, -1,  1};

__global__ __launch_bounds__(256) void shift_kernel(const float* __restrict__ x,
                                                    float* __restrict__ out) {
    const int tid  = threadIdx.x;
    const int wq   = tid & 15;        // which float4 within the row (0..15)
    const int hloc = tid >> 4;        // row within this block's 16-row slab

    const int blk = blockIdx.x;
    const int h   = ((blk & 3) << 4) + hloc;   // 4 slabs per plane
    const int bc  = blk >> 2;                  // fused (b, c) plane index

    // channel within C (bc = b*288 + c); only need c mod 288 for group id
    const int c = bc - (bc / SH_C) * SH_C;
    const int g = c >> SH_CPG_SHIFT;

    const long plane = (long)bc * (SH_H * SH_W);
    float4* dst = reinterpret_cast<float4*>(out + plane + h * SH_W) + wq;

    if (g >= 8) {                     // zero group (channels 256..287)
        *dst = make_float4(0.f, 0.f, 0.f, 0.f);
        return;
    }

    const int dh = c_dh[g];
    const int dw = c_dw[g];
    const int hs = h + dh;

    if ((unsigned)hs >= SH_H) {       // source row out of bounds -> zeros
        *dst = make_float4(0.f, 0.f, 0.f, 0.f);
        return;
    }

    const float* __restrict__ row = x + plane + hs * SH_W;

    float4 v;
    if (dw == 0) {
        // aligned vector load, fully coalesced
        v = reinterpret_cast<const float4*>(row)[wq];
    } else {
        // shifted by +/-1 column: 4 scalar loads; only row edges need the
        // zero fill. L1 absorbs the overlapping sectors.
        const int w0 = (wq << 2) + dw;
        float t[4];
#pragma unroll
        for (int k = 0; k < 4; ++k) {
            const int w = w0 + k;
            t[k] = ((unsigned)w < SH_W) ? __ldg(row + w) : 0.f;
        }
        v = make_float4(t[0], t[1], t[2], t[3]);
    }
    *dst = v;
}

extern "C" void kernel_launch(void* const* d_in, const int* in_sizes, int n_in,
                              void* d_out, int out_size) {
    const float* x = (const float*)d_in[0];
    float* out = (float*)d_out;
    // grid: B*C * (H/16) = 32*288*4
    const int grid = 32 * SH_C * (SH_H / 16);
    shift_kernel<<<grid, 256>>>(x, out);
}

// round 2
// speedup vs baseline: 1.0401x; 1.0401x over previous
#include <cuda_runtime.h>

// shift op: x[32, 288, 64, 64] f32, NCHW. cpg = 32.
// group g in 0..7: out[:, g*32+(0..31), h, w] = x[same ch, h+dh, w+dw] (0 outside)
// group 8 (c in [256,288)): zeros.
//
// One block = one (b,c) plane (64x64). 256 threads, each thread handles 4
// aligned float4 quads at rows {r, r+16, r+32, r+48}, same quad index wq.
// dw=+/-1 quads are rebuilt from the aligned quad + one shuffled component,
// so every global load is an aligned LDG.128 and every 16B is read once.

#define SH_H 64
#define SH_W 64
#define SH_C 288

__constant__ int c_dh[8] = {-1,  1,  0,  0, -1, -1,  1,  1};
__constant__ int c_dw[8] = { 0,  0, -1,  1, -1,  1, -1,  1};

__global__ __launch_bounds__(256) void shift_kernel(const float* __restrict__ x,
                                                    float* __restrict__ out) {
    const int tid   = threadIdx.x;
    const int wq    = tid & 15;        // quad index within row (0..15)
    const int rbase = tid >> 4;        // 0..15; rows rbase + {0,16,32,48}

    const int bc = blockIdx.x;         // fused (b, c) plane index
    const int c  = bc - (bc / SH_C) * SH_C;
    const int g  = c >> 5;             // cpg = 32

    const long plane = (long)bc * (SH_H * SH_W);
    float4* __restrict__ dstp = reinterpret_cast<float4*>(out + plane) + wq;

    const float4 zero = make_float4(0.f, 0.f, 0.f, 0.f);

    if (g >= 8) {                      // zero group (channels 256..287)
#pragma unroll
        for (int i = 0; i < 4; ++i) {
            const int h = rbase + (i << 4);
            __stcs(dstp + h * (SH_W / 4), zero);
        }
        return;
    }

    const int dh = c_dh[g];
    const int dw = c_dw[g];

    const float4* __restrict__ srcp = reinterpret_cast<const float4*>(x + plane) + wq;

    // Issue all 4 aligned loads first (MLP=4). OOB source rows -> zero quad.
    float4 q[4];
#pragma unroll
    for (int i = 0; i < 4; ++i) {
        const int hs = rbase + (i << 4) + dh;
        q[i] = ((unsigned)hs < SH_H) ? __ldcs(srcp + hs * (SH_W / 4)) : zero;
    }

    if (dw == 0) {
#pragma unroll
        for (int i = 0; i < 4; ++i) {
            const int h = rbase + (i << 4);
            __stcs(dstp + h * (SH_W / 4), q[i]);
        }
    } else if (dw > 0) {
        // out quad = {q.y, q.z, q.w, next_lane.q.x}; wq==15 -> last elem = 0
#pragma unroll
        for (int i = 0; i < 4; ++i) {
            float nx = __shfl_down_sync(0xffffffffu, q[i].x, 1);
            if (wq == 15) nx = 0.f;
            const int h = rbase + (i << 4);
            __stcs(dstp + h * (SH_W / 4), make_float4(q[i].y, q[i].z, q[i].w, nx));
        }
    } else {
        // out quad = {prev_lane.q.w, q.x, q.y, q.z}; wq==0 -> first elem = 0
#pragma unroll
        for (int i = 0; i < 4; ++i) {
            float pw = __shfl_up_sync(0xffffffffu, q[i].w, 1);
            if (wq == 0) pw = 0.f;
            const int h = rbase + (i << 4);
            __stcs(dstp + h * (SH_W / 4), make_float4(pw, q[i].x, q[i].y, q[i].z));
        }
    }
}

extern "C" void kernel_launch(void* const* d_in, const int* in_sizes, int n_in,
                              void* d_out, int out_size) {
    const float* x = (const float*)d_in[0];
    float* out = (float*)d_out;
    const int grid = 32 * SH_C;   // one block per (b, c) plane
    shift_kernel<<<grid, 256>>>(x, out);
}